// round 14
// baseline (speedup 1.0000x reference)
#include <cuda_runtime.h>
#include <cuda_fp16.h>

#define NMAX 50000
#define EMAX 800000
#define GROW 512   // 32 h * 16 o
#define NODES_PER_BLOCK 64

// Scratch (static device globals -- no runtime allocation)
__device__ __align__(16) __half g_half[(size_t)NMAX * GROW];  // ~51.2 MB, permuted fp16
__device__ __align__(16) __half h_buf[(size_t)EMAX * 32];     // ~51.2 MB, per-edge hidden
__device__ __align__(16) float w2p[16 * GROW];                // permuted fp32 w2
__device__ __align__(16) float xb_buf[NMAX * 16];
__device__ __align__(16) float sum_buf[NMAX * 16];
__device__ int   deg_dst[NMAX];
__device__ __align__(16) int2 ed_pair[EMAX];  // (src, dst); 16B-aligned for int4 pair loads
__device__ int   idx_is64;

// ---------------------------------------------------------------------------
// Fused setup: zero sum/deg, permute w2, detect edge_index dtype.
// ---------------------------------------------------------------------------
__global__ void setup_kernel(const float* __restrict__ w2,
                             const int* __restrict__ raw_idx, int N) {
    int i = blockIdx.x * blockDim.x + threadIdx.x;
    if (i < N * 16) sum_buf[i] = 0.f;
    if (i < N) deg_dst[i] = 0;

    if (i < 16 * GROW) {
        // w2p[i*512 + pos] = w2[h*256 + i*16 + o],
        // pos(h,o) = ((h&15)>>3)*256 + ((h>>4)*16 + o)*8 + (h&7)
        int ii  = i >> 9;
        int pos = i & 511;
        int j  = pos >> 8;
        int q  = (pos >> 3) & 31;
        int hb = q >> 4;
        int o  = q & 15;
        int p  = pos & 7;
        int h  = hb * 16 + j * 8 + p;
        w2p[i] = w2[h * 256 + ii * 16 + o];
    }

    if (blockIdx.x == 0 && threadIdx.x < 32) {
        int v = raw_idx[1 + 2 * threadIdx.x];
        unsigned m = __ballot_sync(0xffffffffu, v != 0);
        if (threadIdx.x == 0) idx_is64 = (m == 0u);
    }
}

// ---------------------------------------------------------------------------
// Fused decode + layer-1 producer: persistent warps, 2 edges/iteration.
//  - lanes 0/1 decode (src,dst), store ed_pair, bump in-degree hist
//  - all lanes compute h[lane] = relu(ea[e]@w1 + b1)[lane] in fp32,
//    pack neighbor pairs to fp16, even lanes store -> h_buf[e][0..31]
// ---------------------------------------------------------------------------
__global__ void __launch_bounds__(256, 5)
decode_h_kernel(const void* __restrict__ raw,
                const float* __restrict__ ea,
                const float* __restrict__ w1,
                const float* __restrict__ b1,
                int E) {
    int lane = threadIdx.x & 31;
    int gwarp = (blockIdx.x * (blockDim.x >> 5)) + (threadIdx.x >> 5);
    int nwarps = gridDim.x * (blockDim.x >> 5);

    float w1r[16];
#pragma unroll
    for (int i = 0; i < 16; i++) w1r[i] = w1[i * 32 + lane];
    float b1r = b1[lane];
    int is64 = idx_is64;

    int stride = 2 * nwarps;
    for (int e = gwarp * 2; e < E; e += stride) {
        int n2 = min(2, E - e);
        if (lane < n2) {
            int ee = e + lane;
            int s, d;
            if (is64) {
                s = (int)((const long long*)raw)[ee];
                d = (int)((const long long*)raw)[(size_t)E + ee];
            } else {
                s = ((const int*)raw)[ee];
                d = ((const int*)raw)[E + ee];
            }
            ed_pair[ee] = make_int2(s, d);
            atomicAdd(&deg_dst[d], 1);
        }
#pragma unroll
        for (int k = 0; k < 2; k++) {
            if (k >= n2) break;
            int ee = e + k;
            const float4* ea4 = reinterpret_cast<const float4*>(ea + (size_t)ee * 16);
            float a0 = b1r, a1 = 0.f;
            {
                float4 v = ea4[0];
                a0 = fmaf(v.x, w1r[0],  a0);  a1 = fmaf(v.y, w1r[1],  a1);
                a0 = fmaf(v.z, w1r[2],  a0);  a1 = fmaf(v.w, w1r[3],  a1);
            }
            {
                float4 v = ea4[1];
                a0 = fmaf(v.x, w1r[4],  a0);  a1 = fmaf(v.y, w1r[5],  a1);
                a0 = fmaf(v.z, w1r[6],  a0);  a1 = fmaf(v.w, w1r[7],  a1);
            }
            {
                float4 v = ea4[2];
                a0 = fmaf(v.x, w1r[8],  a0);  a1 = fmaf(v.y, w1r[9],  a1);
                a0 = fmaf(v.z, w1r[10], a0);  a1 = fmaf(v.w, w1r[11], a1);
            }
            {
                float4 v = ea4[3];
                a0 = fmaf(v.x, w1r[12], a0);  a1 = fmaf(v.y, w1r[13], a1);
                a0 = fmaf(v.z, w1r[14], a0);  a1 = fmaf(v.w, w1r[15], a1);
            }
            float h = fmaxf(a0 + a1, 0.f);
            float hn = __shfl_xor_sync(0xffffffffu, h, 1);  // neighbor's h
            if (!(lane & 1)) {
                __half2 hp = __floats2half2_rn(h, hn);      // (h[2m], h[2m+1])
                reinterpret_cast<unsigned*>(h_buf)[(size_t)ee * 16 + (lane >> 1)] =
                    *reinterpret_cast<unsigned*>(&hp);
            }
        }
    }
}

// ---------------------------------------------------------------------------
// Per-node precompute: block of 128 threads handles 64 nodes.
// w2p staged in smem. Thread t owns 4 CONTIGUOUS permuted outputs ->
// one coalesced 8B fp16 store per node. fp32 math.
// ---------------------------------------------------------------------------
__global__ void node_pre_kernel(const float* __restrict__ x,
                                const float* __restrict__ b2,
                                int N) {
    __shared__ float w2s[16 * GROW];            // 32 KB
    __shared__ float xs[NODES_PER_BLOCK * 16];  // 4 KB
    __shared__ float b2s[256];                  // 1 KB
    int t = threadIdx.x;                        // 0..127

    for (int j = t; j < 16 * GROW / 4; j += 128)
        reinterpret_cast<float4*>(w2s)[j] = reinterpret_cast<const float4*>(w2p)[j];
    for (int j = t; j < 256; j += 128) b2s[j] = b2[j];

    int nbase = blockIdx.x * NODES_PER_BLOCK;
    int ncnt  = min(NODES_PER_BLOCK, N - nbase);
    for (int j = t; j < ncnt * 16; j += 128) xs[j] = x[nbase * 16 + j];
    __syncthreads();

    for (int ln = 0; ln < ncnt; ln++) {
        int n = nbase + ln;
        const float4* xr = reinterpret_cast<const float4*>(xs + ln * 16);
        float4 xa = xr[0], xbv = xr[1], xc = xr[2], xd = xr[3];

        float4 acc = make_float4(0.f, 0.f, 0.f, 0.f);
#pragma unroll
        for (int i = 0; i < 16; i++) {
            float xi;
            switch (i >> 2) {
                case 0: xi = (i & 3) == 0 ? xa.x : (i & 3) == 1 ? xa.y : (i & 3) == 2 ? xa.z : xa.w; break;
                case 1: xi = (i & 3) == 0 ? xbv.x : (i & 3) == 1 ? xbv.y : (i & 3) == 2 ? xbv.z : xbv.w; break;
                case 2: xi = (i & 3) == 0 ? xc.x : (i & 3) == 1 ? xc.y : (i & 3) == 2 ? xc.z : xc.w; break;
                default: xi = (i & 3) == 0 ? xd.x : (i & 3) == 1 ? xd.y : (i & 3) == 2 ? xd.z : xd.w; break;
            }
            float4 w = reinterpret_cast<const float4*>(w2s + i * GROW)[t];
            acc.x = fmaf(xi, w.x, acc.x);
            acc.y = fmaf(xi, w.y, acc.y);
            acc.z = fmaf(xi, w.z, acc.z);
            acc.w = fmaf(xi, w.w, acc.w);
        }

        __half2 h0 = __floats2half2_rn(acc.x, acc.y);
        __half2 h1 = __floats2half2_rn(acc.z, acc.w);
        uint2 pk;
        pk.x = *reinterpret_cast<unsigned*>(&h0);
        pk.y = *reinterpret_cast<unsigned*>(&h1);
        *reinterpret_cast<uint2*>(g_half + (size_t)n * GROW + t * 4) = pk;

        if (t < 16) {
            const float* xrs = xs + ln * 16;
            float a = 0.f;
#pragma unroll
            for (int i = 0; i < 16; i++) a = fmaf(xrs[i], b2s[i * 16 + t], a);
            xb_buf[n * 16 + t] = a;
        }
    }
}

// ---------------------------------------------------------------------------
// Edge message: NO shuffles for h — lane l broadcast-loads the 16 halves it
// needs (units b..b+15, b=lane&16) as 2 uint4; they pair element-for-element
// with the permuted G uint4s. 8 fp16 mul/fma ops, fp32 final reduction.
// ---------------------------------------------------------------------------
__device__ __forceinline__ float edge_msg(int e, int src, int lane) {
    const uint4* H = reinterpret_cast<const uint4*>(h_buf + (size_t)e * 32);
    int hi = (lane & 16) >> 3;                  // 0 or 2 (uint4 index)
    uint4 ha = H[hi];
    uint4 hbv = H[hi + 1];
    const uint4* G16 = reinterpret_cast<const uint4*>(
        g_half + (size_t)src * GROW) + lane;
    uint4 ga = G16[0];
    uint4 gb = G16[32];

    const __half2* hA = reinterpret_cast<const __half2*>(&ha);
    const __half2* hB = reinterpret_cast<const __half2*>(&hbv);
    const __half2* gA = reinterpret_cast<const __half2*>(&ga);
    const __half2* gB = reinterpret_cast<const __half2*>(&gb);

    __half2 acc0 = __hmul2(hA[0], gA[0]);
    __half2 acc1 = __hmul2(hA[1], gA[1]);
    __half2 acc2 = __hmul2(hA[2], gA[2]);
    __half2 acc3 = __hmul2(hA[3], gA[3]);
    acc0 = __hfma2(hB[0], gB[0], acc0);
    acc1 = __hfma2(hB[1], gB[1], acc1);
    acc2 = __hfma2(hB[2], gB[2], acc2);
    acc3 = __hfma2(hB[3], gB[3], acc3);

    float2 f0 = __half22float2(acc0);
    float2 f1 = __half22float2(acc1);
    float2 f2 = __half22float2(acc2);
    float2 f3 = __half22float2(acc3);
    float partial = ((f0.x + f0.y) + (f1.x + f1.y))
                  + ((f2.x + f2.y) + (f3.x + f3.y));
    partial += __shfl_xor_sync(0xffffffffu, partial, 16);

    return partial + xb_buf[src * 16 + (lane & 15)];
}

// gather 4 consecutive o's into lanes 0,4,8,12 and issue one RED.128
__device__ __forceinline__ void scatter_msg(float msg, int dst, int lane) {
    float m1 = __shfl_down_sync(0xffffffffu, msg, 1);
    float m2 = __shfl_down_sync(0xffffffffu, msg, 2);
    float m3 = __shfl_down_sync(0xffffffffu, msg, 3);
    if (lane < 16 && (lane & 3) == 0) {
        float* dstp = sum_buf + (size_t)dst * 16 + lane;
        asm volatile("red.global.v4.f32.add [%0], {%1, %2, %3, %4};"
                     :: "l"(dstp), "f"(msg), "f"(m1), "f"(m2), "f"(m3)
                     : "memory");
    }
}

// ---------------------------------------------------------------------------
// Edge scatter kernel: persistent warps, 2 edges/iteration, REDs deferred.
// No w1/layer-1 -> low registers; __launch_bounds__(256,6) = 75% occupancy.
// ---------------------------------------------------------------------------
__global__ void __launch_bounds__(256, 6)
edge_kernel(int E) {
    int lane = threadIdx.x & 31;
    int gwarp = (blockIdx.x * (blockDim.x >> 5)) + (threadIdx.x >> 5);
    int nwarps = gridDim.x * (blockDim.x >> 5);

    int stride = 2 * nwarps;
    int e = gwarp * 2;
    for (; e + 2 <= E; e += stride) {
        int4 p = *reinterpret_cast<const int4*>(&ed_pair[e]);   // e even -> aligned
        float m0 = edge_msg(e,     p.x, lane);
        float m1 = edge_msg(e + 1, p.z, lane);
        scatter_msg(m0, p.y, lane);
        scatter_msg(m1, p.w, lane);
    }
    if (e < E) {
        int2 sd = ed_pair[e];
        float m = edge_msg(e, sd.x, lane);
        scatter_msg(m, sd.y, lane);
    }
}

// ---------------------------------------------------------------------------
// Finalize: out[n][o] = sum[n][o]/max(indeg,1) + x[n]@root[:,o] + bias[o]
// ---------------------------------------------------------------------------
__global__ void finalize_kernel(const float* __restrict__ x,
                                const float* __restrict__ root,
                                const float* __restrict__ bias,
                                float* __restrict__ out, int N) {
    int idx = blockIdx.x * blockDim.x + threadIdx.x;
    if (idx >= N * 16) return;
    int n = idx >> 4;
    int o = idx & 15;
    float c = (float)deg_dst[n];
    float a = sum_buf[idx] / fmaxf(c, 1.0f);
    float r = 0.f;
#pragma unroll
    for (int i = 0; i < 16; i++) r = fmaf(x[n * 16 + i], root[i * 16 + o], r);
    out[idx] = a + r + bias[o];
}

extern "C" void kernel_launch(void* const* d_in, const int* in_sizes, int n_in,
                              void* d_out, int out_size) {
    const float* x    = (const float*)d_in[0];
    const void*  ei   = d_in[1];
    const float* ea   = (const float*)d_in[2];
    const float* w1   = (const float*)d_in[3];
    const float* b1   = (const float*)d_in[4];
    const float* w2   = (const float*)d_in[5];
    const float* b2   = (const float*)d_in[6];
    const float* root = (const float*)d_in[7];
    const float* bias = (const float*)d_in[8];
    float*       out  = (float*)d_out;

    int N = in_sizes[0] / 16;
    int E = in_sizes[2] / 16;

    setup_kernel<<<(N * 16 + 255) / 256, 256>>>(w2, (const int*)ei, N);
    decode_h_kernel<<<2048, 256>>>(ei, ea, w1, b1, E);

    node_pre_kernel<<<(N + NODES_PER_BLOCK - 1) / NODES_PER_BLOCK, 128>>>(x, b2, N);

    edge_kernel<<<2048, 256>>>(E);

    finalize_kernel<<<(N * 16 + 255) / 256, 256>>>(x, root, bias, out, N);
}

// round 15
// speedup vs baseline: 1.3112x; 1.3112x over previous
#include <cuda_runtime.h>
#include <cuda_fp16.h>

#define NMAX 50000
#define EMAX 800000
#define GROW 512   // 32 h * 16 o
#define NODES_PER_BLOCK 64

// Scratch (static device globals -- no runtime allocation)
__device__ __align__(16) __half g_half[(size_t)NMAX * GROW];  // ~51.2 MB, permuted fp16
__device__ __align__(16) float w2p[16 * GROW];                // permuted fp32 w2
__device__ __align__(16) float xb_buf[NMAX * 16];
__device__ __align__(16) float sum_buf[NMAX * 16];
__device__ int   deg_dst[NMAX];
__device__ __align__(16) int2 ed_pair[EMAX];  // (src, dst); 16B-aligned for int4 pair loads
__device__ int   idx_is64;

// ---------------------------------------------------------------------------
// Fused setup: zero sum/deg, permute w2, detect edge_index dtype.
// ---------------------------------------------------------------------------
__global__ void setup_kernel(const float* __restrict__ w2,
                             const int* __restrict__ raw_idx, int N) {
    int i = blockIdx.x * blockDim.x + threadIdx.x;
    if (i < N * 16) sum_buf[i] = 0.f;
    if (i < N) deg_dst[i] = 0;

    if (i < 16 * GROW) {
        // w2p[i*512 + pos] = w2[h*256 + i*16 + o],
        // pos(h,o) = ((h&15)>>3)*256 + ((h>>4)*16 + o)*8 + (h&7)
        int ii  = i >> 9;
        int pos = i & 511;
        int j  = pos >> 8;
        int q  = (pos >> 3) & 31;
        int hb = q >> 4;
        int o  = q & 15;
        int p  = pos & 7;
        int h  = hb * 16 + j * 8 + p;
        w2p[i] = w2[h * 256 + ii * 16 + o];
    }

    if (blockIdx.x == 0 && threadIdx.x < 32) {
        int v = raw_idx[1 + 2 * threadIdx.x];
        unsigned m = __ballot_sync(0xffffffffu, v != 0);
        if (threadIdx.x == 0) idx_is64 = (m == 0u);
    }
}

// ---------------------------------------------------------------------------
// Decode edge_index into packed int2 (src, dst) AND build in-degree histogram.
// ---------------------------------------------------------------------------
__global__ void decode_hist_kernel(const void* __restrict__ raw, int E) {
    int e = blockIdx.x * blockDim.x + threadIdx.x;
    if (e >= E) return;
    int s, d;
    if (idx_is64) {
        s = (int)((const long long*)raw)[e];
        d = (int)((const long long*)raw)[E + e];
    } else {
        s = ((const int*)raw)[e];
        d = ((const int*)raw)[E + e];
    }
    ed_pair[e] = make_int2(s, d);
    atomicAdd(&deg_dst[d], 1);
}

// ---------------------------------------------------------------------------
// Per-node precompute: block of 128 threads handles 64 nodes.
// w2p staged in smem. Thread t owns 4 CONTIGUOUS permuted outputs ->
// one coalesced 8B fp16 store per node. fp32 math.
// ---------------------------------------------------------------------------
__global__ void node_pre_kernel(const float* __restrict__ x,
                                const float* __restrict__ b2,
                                int N) {
    __shared__ float w2s[16 * GROW];            // 32 KB
    __shared__ float xs[NODES_PER_BLOCK * 16];  // 4 KB
    __shared__ float b2s[256];                  // 1 KB
    int t = threadIdx.x;                        // 0..127

    for (int j = t; j < 16 * GROW / 4; j += 128)
        reinterpret_cast<float4*>(w2s)[j] = reinterpret_cast<const float4*>(w2p)[j];
    for (int j = t; j < 256; j += 128) b2s[j] = b2[j];

    int nbase = blockIdx.x * NODES_PER_BLOCK;
    int ncnt  = min(NODES_PER_BLOCK, N - nbase);
    for (int j = t; j < ncnt * 16; j += 128) xs[j] = x[nbase * 16 + j];
    __syncthreads();

    for (int ln = 0; ln < ncnt; ln++) {
        int n = nbase + ln;
        const float4* xr = reinterpret_cast<const float4*>(xs + ln * 16);
        float4 xa = xr[0], xbv = xr[1], xc = xr[2], xd = xr[3];

        float4 acc = make_float4(0.f, 0.f, 0.f, 0.f);
#pragma unroll
        for (int i = 0; i < 16; i++) {
            float xi;
            switch (i >> 2) {
                case 0: xi = (i & 3) == 0 ? xa.x : (i & 3) == 1 ? xa.y : (i & 3) == 2 ? xa.z : xa.w; break;
                case 1: xi = (i & 3) == 0 ? xbv.x : (i & 3) == 1 ? xbv.y : (i & 3) == 2 ? xbv.z : xbv.w; break;
                case 2: xi = (i & 3) == 0 ? xc.x : (i & 3) == 1 ? xc.y : (i & 3) == 2 ? xc.z : xc.w; break;
                default: xi = (i & 3) == 0 ? xd.x : (i & 3) == 1 ? xd.y : (i & 3) == 2 ? xd.z : xd.w; break;
            }
            float4 w = reinterpret_cast<const float4*>(w2s + i * GROW)[t];
            acc.x = fmaf(xi, w.x, acc.x);
            acc.y = fmaf(xi, w.y, acc.y);
            acc.z = fmaf(xi, w.z, acc.z);
            acc.w = fmaf(xi, w.w, acc.w);
        }

        __half2 h0 = __floats2half2_rn(acc.x, acc.y);
        __half2 h1 = __floats2half2_rn(acc.z, acc.w);
        uint2 pk;
        pk.x = *reinterpret_cast<unsigned*>(&h0);
        pk.y = *reinterpret_cast<unsigned*>(&h1);
        *reinterpret_cast<uint2*>(g_half + (size_t)n * GROW + t * 4) = pk;

        if (t < 16) {
            const float* xrs = xs + ln * 16;
            float a = 0.f;
#pragma unroll
            for (int i = 0; i < 16; i++) a = fmaf(xrs[i], b2s[i * 16 + t], a);
            xb_buf[n * 16 + t] = a;
        }
    }
}

// ---------------------------------------------------------------------------
// layer-1: lane l owns hidden unit l; ea via uniform float4 loads.
// ---------------------------------------------------------------------------
__device__ __forceinline__ float layer1(int e,
                                        const float* __restrict__ ea,
                                        const float* __restrict__ w1r,
                                        float b1r) {
    const float4* ea4 = reinterpret_cast<const float4*>(ea + (size_t)e * 16);
    float a0 = b1r, a1 = 0.f;
    {
        float4 v = ea4[0];
        a0 = fmaf(v.x, w1r[0],  a0);  a1 = fmaf(v.y, w1r[1],  a1);
        a0 = fmaf(v.z, w1r[2],  a0);  a1 = fmaf(v.w, w1r[3],  a1);
    }
    {
        float4 v = ea4[1];
        a0 = fmaf(v.x, w1r[4],  a0);  a1 = fmaf(v.y, w1r[5],  a1);
        a0 = fmaf(v.z, w1r[6],  a0);  a1 = fmaf(v.w, w1r[7],  a1);
    }
    {
        float4 v = ea4[2];
        a0 = fmaf(v.x, w1r[8],  a0);  a1 = fmaf(v.y, w1r[9],  a1);
        a0 = fmaf(v.z, w1r[10], a0);  a1 = fmaf(v.w, w1r[11], a1);
    }
    {
        float4 v = ea4[3];
        a0 = fmaf(v.x, w1r[12], a0);  a1 = fmaf(v.y, w1r[13], a1);
        a0 = fmaf(v.z, w1r[14], a0);  a1 = fmaf(v.w, w1r[15], a1);
    }
    return fmaxf(a0 + a1, 0.f);
}

// ---------------------------------------------------------------------------
// Contraction from smem-resident h (validated R14 mapping): lane l
// broadcast-loads its 2 needed uint4s (halves b..b+15, b=lane&16); pairs
// align element-for-element with permuted G uint4s. fp16 mul/fma, fp32 tail.
// ---------------------------------------------------------------------------
__device__ __forceinline__ float contract_msg(const unsigned* __restrict__ hw,
                                              int off4, int src, int lane) {
    const uint4* Hs = reinterpret_cast<const uint4*>(hw);
    int hi = off4 + ((lane & 16) >> 3);          // off4 + {0,2}
    uint4 ha  = Hs[hi];
    uint4 hbv = Hs[hi + 1];
    const uint4* G16 = reinterpret_cast<const uint4*>(
        g_half + (size_t)src * GROW) + lane;
    uint4 ga = G16[0];
    uint4 gb = G16[32];

    const __half2* hA = reinterpret_cast<const __half2*>(&ha);
    const __half2* hB = reinterpret_cast<const __half2*>(&hbv);
    const __half2* gA = reinterpret_cast<const __half2*>(&ga);
    const __half2* gB = reinterpret_cast<const __half2*>(&gb);

    __half2 acc0 = __hmul2(hA[0], gA[0]);
    __half2 acc1 = __hmul2(hA[1], gA[1]);
    __half2 acc2 = __hmul2(hA[2], gA[2]);
    __half2 acc3 = __hmul2(hA[3], gA[3]);
    acc0 = __hfma2(hB[0], gB[0], acc0);
    acc1 = __hfma2(hB[1], gB[1], acc1);
    acc2 = __hfma2(hB[2], gB[2], acc2);
    acc3 = __hfma2(hB[3], gB[3], acc3);

    float2 f0 = __half22float2(acc0);
    float2 f1 = __half22float2(acc1);
    float2 f2 = __half22float2(acc2);
    float2 f3 = __half22float2(acc3);
    float partial = ((f0.x + f0.y) + (f1.x + f1.y))
                  + ((f2.x + f2.y) + (f3.x + f3.y));
    partial += __shfl_xor_sync(0xffffffffu, partial, 16);

    return partial + xb_buf[src * 16 + (lane & 15)];
}

// gather 4 consecutive o's into lanes 0,4,8,12 and issue one RED.128
__device__ __forceinline__ void scatter_msg(float msg, int dst, int lane) {
    float m1 = __shfl_down_sync(0xffffffffu, msg, 1);
    float m2 = __shfl_down_sync(0xffffffffu, msg, 2);
    float m3 = __shfl_down_sync(0xffffffffu, msg, 3);
    if (lane < 16 && (lane & 3) == 0) {
        float* dstp = sum_buf + (size_t)dst * 16 + lane;
        asm volatile("red.global.v4.f32.add [%0], {%1, %2, %3, %4};"
                     :: "l"(dstp), "f"(msg), "f"(m1), "f"(m2), "f"(m3)
                     : "memory");
    }
}

// ---------------------------------------------------------------------------
// Fused edge kernel: persistent warps, 2 edges/iteration.
//   phase 1: layer-1 for both edges (fp32, reg-resident w1) -> pack to smem
//   phase 2: broadcast-LDS h + G loads + fp16 contraction, deferred RED.128
// ---------------------------------------------------------------------------
__global__ void __launch_bounds__(256, 5)
edge_kernel(const float* __restrict__ ea,
            const float* __restrict__ w1,
            const float* __restrict__ b1,
            int E) {
    __shared__ __align__(16) unsigned hsm[8][32];   // per-warp: 2 edges x 16 words
    int lane = threadIdx.x & 31;
    int warp = threadIdx.x >> 5;
    unsigned* hw = hsm[warp];
    int gwarp = (blockIdx.x * (blockDim.x >> 5)) + warp;
    int nwarps = gridDim.x * (blockDim.x >> 5);

    float w1r[16];
#pragma unroll
    for (int i = 0; i < 16; i++) w1r[i] = w1[i * 32 + lane];
    float b1r = b1[lane];

    int stride = 2 * nwarps;
    int e = gwarp * 2;
    for (; e + 2 <= E; e += stride) {
        int4 p = *reinterpret_cast<const int4*>(&ed_pair[e]);   // e even -> aligned

        float h0 = layer1(e,     ea, w1r, b1r);
        float h1 = layer1(e + 1, ea, w1r, b1r);
        float hn0 = __shfl_xor_sync(0xffffffffu, h0, 1);
        float hn1 = __shfl_xor_sync(0xffffffffu, h1, 1);
        if (!(lane & 1)) {
            __half2 q0 = __floats2half2_rn(h0, hn0);
            __half2 q1 = __floats2half2_rn(h1, hn1);
            hw[lane >> 1]        = *reinterpret_cast<unsigned*>(&q0);
            hw[16 + (lane >> 1)] = *reinterpret_cast<unsigned*>(&q1);
        }
        __syncwarp();

        float m0 = contract_msg(hw, 0, p.x, lane);
        float m1 = contract_msg(hw, 4, p.z, lane);
        __syncwarp();          // all reads done before next iteration's stores

        scatter_msg(m0, p.y, lane);
        scatter_msg(m1, p.w, lane);
    }
    if (e < E) {
        int2 sd = ed_pair[e];
        float h0 = layer1(e, ea, w1r, b1r);
        float hn0 = __shfl_xor_sync(0xffffffffu, h0, 1);
        if (!(lane & 1)) {
            __half2 q0 = __floats2half2_rn(h0, hn0);
            hw[lane >> 1] = *reinterpret_cast<unsigned*>(&q0);
        }
        __syncwarp();
        float m0 = contract_msg(hw, 0, sd.x, lane);
        scatter_msg(m0, sd.y, lane);
    }
}

// ---------------------------------------------------------------------------
// Finalize: out[n][o] = sum[n][o]/max(indeg,1) + x[n]@root[:,o] + bias[o]
// ---------------------------------------------------------------------------
__global__ void finalize_kernel(const float* __restrict__ x,
                                const float* __restrict__ root,
                                const float* __restrict__ bias,
                                float* __restrict__ out, int N) {
    int idx = blockIdx.x * blockDim.x + threadIdx.x;
    if (idx >= N * 16) return;
    int n = idx >> 4;
    int o = idx & 15;
    float c = (float)deg_dst[n];
    float a = sum_buf[idx] / fmaxf(c, 1.0f);
    float r = 0.f;
#pragma unroll
    for (int i = 0; i < 16; i++) r = fmaf(x[n * 16 + i], root[i * 16 + o], r);
    out[idx] = a + r + bias[o];
}

extern "C" void kernel_launch(void* const* d_in, const int* in_sizes, int n_in,
                              void* d_out, int out_size) {
    const float* x    = (const float*)d_in[0];
    const void*  ei   = d_in[1];
    const float* ea   = (const float*)d_in[2];
    const float* w1   = (const float*)d_in[3];
    const float* b1   = (const float*)d_in[4];
    const float* w2   = (const float*)d_in[5];
    const float* b2   = (const float*)d_in[6];
    const float* root = (const float*)d_in[7];
    const float* bias = (const float*)d_in[8];
    float*       out  = (float*)d_out;

    int N = in_sizes[0] / 16;
    int E = in_sizes[2] / 16;

    setup_kernel<<<(N * 16 + 255) / 256, 256>>>(w2, (const int*)ei, N);
    decode_hist_kernel<<<(E + 255) / 256, 256>>>(ei, E);

    node_pre_kernel<<<(N + NODES_PER_BLOCK - 1) / NODES_PER_BLOCK, 128>>>(x, b2, N);

    edge_kernel<<<2048, 256>>>(ea, w1, b1, E);

    finalize_kernel<<<(N * 16 + 255) / 256, 256>>>(x, root, bias, out, N);
}

// round 16
// speedup vs baseline: 1.3249x; 1.0105x over previous
#include <cuda_runtime.h>
#include <cuda_fp16.h>

#define NMAX 50000
#define EMAX 800000
#define GROW 512   // 32 h * 16 o
#define NODES_PER_BLOCK 64

// Scratch (static device globals -- no runtime allocation)
__device__ __align__(16) __half g_half[(size_t)NMAX * GROW];  // ~51.2 MB, permuted fp16
__device__ __align__(16) float w2p[16 * GROW];                // permuted fp32 w2
__device__ __align__(16) float xb_buf[NMAX * 16];
__device__ __align__(16) float sum_buf[NMAX * 16];
__device__ int   deg_dst[NMAX];
__device__ __align__(16) int2 ed_pair[EMAX];  // (src, dst); 16B-aligned for int4 pair loads
__device__ int   idx_is64;

// ---------------------------------------------------------------------------
// Fused setup: zero sum/deg, permute w2, detect edge_index dtype.
// ---------------------------------------------------------------------------
__global__ void setup_kernel(const float* __restrict__ w2,
                             const int* __restrict__ raw_idx, int N) {
    int i = blockIdx.x * blockDim.x + threadIdx.x;
    if (i < N * 16) sum_buf[i] = 0.f;
    if (i < N) deg_dst[i] = 0;

    if (i < 16 * GROW) {
        // w2p[i*512 + pos] = w2[h*256 + i*16 + o],
        // pos(h,o) = ((h&15)>>3)*256 + ((h>>4)*16 + o)*8 + (h&7)
        int ii  = i >> 9;
        int pos = i & 511;
        int j  = pos >> 8;
        int q  = (pos >> 3) & 31;
        int hb = q >> 4;
        int o  = q & 15;
        int p  = pos & 7;
        int h  = hb * 16 + j * 8 + p;
        w2p[i] = w2[h * 256 + ii * 16 + o];
    }

    if (blockIdx.x == 0 && threadIdx.x < 32) {
        int v = raw_idx[1 + 2 * threadIdx.x];
        unsigned m = __ballot_sync(0xffffffffu, v != 0);
        if (threadIdx.x == 0) idx_is64 = (m == 0u);
    }
}

// ---------------------------------------------------------------------------
// Decode edge_index into packed int2 (src, dst) AND build in-degree histogram.
// ---------------------------------------------------------------------------
__global__ void decode_hist_kernel(const void* __restrict__ raw, int E) {
    int e = blockIdx.x * blockDim.x + threadIdx.x;
    if (e >= E) return;
    int s, d;
    if (idx_is64) {
        s = (int)((const long long*)raw)[e];
        d = (int)((const long long*)raw)[E + e];
    } else {
        s = ((const int*)raw)[e];
        d = ((const int*)raw)[E + e];
    }
    ed_pair[e] = make_int2(s, d);
    atomicAdd(&deg_dst[d], 1);
}

// ---------------------------------------------------------------------------
// Per-node precompute: block of 128 threads handles 64 nodes.
// w2p staged in smem. Thread t owns 4 CONTIGUOUS permuted outputs ->
// one coalesced 8B fp16 store per node. fp32 math.
// ---------------------------------------------------------------------------
__global__ void node_pre_kernel(const float* __restrict__ x,
                                const float* __restrict__ b2,
                                int N) {
    __shared__ float w2s[16 * GROW];            // 32 KB
    __shared__ float xs[NODES_PER_BLOCK * 16];  // 4 KB
    __shared__ float b2s[256];                  // 1 KB
    int t = threadIdx.x;                        // 0..127

    for (int j = t; j < 16 * GROW / 4; j += 128)
        reinterpret_cast<float4*>(w2s)[j] = reinterpret_cast<const float4*>(w2p)[j];
    for (int j = t; j < 256; j += 128) b2s[j] = b2[j];

    int nbase = blockIdx.x * NODES_PER_BLOCK;
    int ncnt  = min(NODES_PER_BLOCK, N - nbase);
    for (int j = t; j < ncnt * 16; j += 128) xs[j] = x[nbase * 16 + j];
    __syncthreads();

    for (int ln = 0; ln < ncnt; ln++) {
        int n = nbase + ln;
        const float4* xr = reinterpret_cast<const float4*>(xs + ln * 16);
        float4 xa = xr[0], xbv = xr[1], xc = xr[2], xd = xr[3];

        float4 acc = make_float4(0.f, 0.f, 0.f, 0.f);
#pragma unroll
        for (int i = 0; i < 16; i++) {
            float xi;
            switch (i >> 2) {
                case 0: xi = (i & 3) == 0 ? xa.x : (i & 3) == 1 ? xa.y : (i & 3) == 2 ? xa.z : xa.w; break;
                case 1: xi = (i & 3) == 0 ? xbv.x : (i & 3) == 1 ? xbv.y : (i & 3) == 2 ? xbv.z : xbv.w; break;
                case 2: xi = (i & 3) == 0 ? xc.x : (i & 3) == 1 ? xc.y : (i & 3) == 2 ? xc.z : xc.w; break;
                default: xi = (i & 3) == 0 ? xd.x : (i & 3) == 1 ? xd.y : (i & 3) == 2 ? xd.z : xd.w; break;
            }
            float4 w = reinterpret_cast<const float4*>(w2s + i * GROW)[t];
            acc.x = fmaf(xi, w.x, acc.x);
            acc.y = fmaf(xi, w.y, acc.y);
            acc.z = fmaf(xi, w.z, acc.z);
            acc.w = fmaf(xi, w.w, acc.w);
        }

        __half2 h0 = __floats2half2_rn(acc.x, acc.y);
        __half2 h1 = __floats2half2_rn(acc.z, acc.w);
        uint2 pk;
        pk.x = *reinterpret_cast<unsigned*>(&h0);
        pk.y = *reinterpret_cast<unsigned*>(&h1);
        *reinterpret_cast<uint2*>(g_half + (size_t)n * GROW + t * 4) = pk;

        if (t < 16) {
            const float* xrs = xs + ln * 16;
            float a = 0.f;
#pragma unroll
            for (int i = 0; i < 16; i++) a = fmaf(xrs[i], b2s[i * 16 + t], a);
            xb_buf[n * 16 + t] = a;
        }
    }
}

// ---------------------------------------------------------------------------
// layer-1: lane l owns hidden unit l; ea via uniform float4 loads.
// ---------------------------------------------------------------------------
__device__ __forceinline__ float layer1(int e,
                                        const float* __restrict__ ea,
                                        const float* __restrict__ w1r,
                                        float b1r) {
    const float4* ea4 = reinterpret_cast<const float4*>(ea + (size_t)e * 16);
    float a0 = b1r, a1 = 0.f;
    {
        float4 v = ea4[0];
        a0 = fmaf(v.x, w1r[0],  a0);  a1 = fmaf(v.y, w1r[1],  a1);
        a0 = fmaf(v.z, w1r[2],  a0);  a1 = fmaf(v.w, w1r[3],  a1);
    }
    {
        float4 v = ea4[1];
        a0 = fmaf(v.x, w1r[4],  a0);  a1 = fmaf(v.y, w1r[5],  a1);
        a0 = fmaf(v.z, w1r[6],  a0);  a1 = fmaf(v.w, w1r[7],  a1);
    }
    {
        float4 v = ea4[2];
        a0 = fmaf(v.x, w1r[8],  a0);  a1 = fmaf(v.y, w1r[9],  a1);
        a0 = fmaf(v.z, w1r[10], a0);  a1 = fmaf(v.w, w1r[11], a1);
    }
    {
        float4 v = ea4[3];
        a0 = fmaf(v.x, w1r[12], a0);  a1 = fmaf(v.y, w1r[13], a1);
        a0 = fmaf(v.z, w1r[14], a0);  a1 = fmaf(v.w, w1r[15], a1);
    }
    return fmaxf(a0 + a1, 0.f);
}

// ---------------------------------------------------------------------------
// Contraction from smem-resident h (validated R14 mapping): lane l
// broadcast-loads its 2 needed uint4s (halves b..b+15, b=lane&16); pairs
// align element-for-element with permuted G uint4s. fp16 mul/fma, fp32 tail.
// ---------------------------------------------------------------------------
__device__ __forceinline__ float contract_msg(const unsigned* __restrict__ hw,
                                              int off4, int src, int lane) {
    const uint4* Hs = reinterpret_cast<const uint4*>(hw);
    int hi = off4 + ((lane & 16) >> 3);          // off4 + {0,2}
    uint4 ha  = Hs[hi];
    uint4 hbv = Hs[hi + 1];
    const uint4* G16 = reinterpret_cast<const uint4*>(
        g_half + (size_t)src * GROW) + lane;
    uint4 ga = G16[0];
    uint4 gb = G16[32];

    const __half2* hA = reinterpret_cast<const __half2*>(&ha);
    const __half2* hB = reinterpret_cast<const __half2*>(&hbv);
    const __half2* gA = reinterpret_cast<const __half2*>(&ga);
    const __half2* gB = reinterpret_cast<const __half2*>(&gb);

    __half2 acc0 = __hmul2(hA[0], gA[0]);
    __half2 acc1 = __hmul2(hA[1], gA[1]);
    __half2 acc2 = __hmul2(hA[2], gA[2]);
    __half2 acc3 = __hmul2(hA[3], gA[3]);
    acc0 = __hfma2(hB[0], gB[0], acc0);
    acc1 = __hfma2(hB[1], gB[1], acc1);
    acc2 = __hfma2(hB[2], gB[2], acc2);
    acc3 = __hfma2(hB[3], gB[3], acc3);

    float2 f0 = __half22float2(acc0);
    float2 f1 = __half22float2(acc1);
    float2 f2 = __half22float2(acc2);
    float2 f3 = __half22float2(acc3);
    float partial = ((f0.x + f0.y) + (f1.x + f1.y))
                  + ((f2.x + f2.y) + (f3.x + f3.y));
    partial += __shfl_xor_sync(0xffffffffu, partial, 16);

    return partial + xb_buf[src * 16 + (lane & 15)];
}

// gather 4 consecutive o's into lanes 0,4,8,12 and issue one RED.128
__device__ __forceinline__ void scatter_msg(float msg, int dst, int lane) {
    float m1 = __shfl_down_sync(0xffffffffu, msg, 1);
    float m2 = __shfl_down_sync(0xffffffffu, msg, 2);
    float m3 = __shfl_down_sync(0xffffffffu, msg, 3);
    if (lane < 16 && (lane & 3) == 0) {
        float* dstp = sum_buf + (size_t)dst * 16 + lane;
        asm volatile("red.global.v4.f32.add [%0], {%1, %2, %3, %4};"
                     :: "l"(dstp), "f"(msg), "f"(m1), "f"(m2), "f"(m3)
                     : "memory");
    }
}

// ---------------------------------------------------------------------------
// Fused edge kernel: persistent warps, FOUR edges/iteration for deep MLP.
//   phase 1: layer-1 x4 (fp32, reg-resident w1) -> pack h to smem
//   phase 2: broadcast-LDS h + G loads + fp16 contraction x4
//   phase 3: deferred RED.128 x4
// __launch_bounds__(256, 4): 64-reg cap -> no spills; 4 blocks/SM.
// ---------------------------------------------------------------------------
__global__ void __launch_bounds__(256, 4)
edge_kernel(const float* __restrict__ ea,
            const float* __restrict__ w1,
            const float* __restrict__ b1,
            int E) {
    __shared__ __align__(16) unsigned hsm[8][64];   // per-warp: 4 edges x 16 words
    int lane = threadIdx.x & 31;
    int warp = threadIdx.x >> 5;
    unsigned* hw = hsm[warp];
    int gwarp = (blockIdx.x * (blockDim.x >> 5)) + warp;
    int nwarps = gridDim.x * (blockDim.x >> 5);

    float w1r[16];
#pragma unroll
    for (int i = 0; i < 16; i++) w1r[i] = w1[i * 32 + lane];
    float b1r = b1[lane];

    int stride = 4 * nwarps;
    int e = gwarp * 4;
    for (; e + 4 <= E; e += stride) {
        // two 16B loads: (src0,dst0,src1,dst1), (src2,dst2,src3,dst3)
        int4 p = *reinterpret_cast<const int4*>(&ed_pair[e]);
        int4 q = *reinterpret_cast<const int4*>(&ed_pair[e + 2]);

        float h0 = layer1(e,     ea, w1r, b1r);
        float h1 = layer1(e + 1, ea, w1r, b1r);
        float h2 = layer1(e + 2, ea, w1r, b1r);
        float h3 = layer1(e + 3, ea, w1r, b1r);
        float n0 = __shfl_xor_sync(0xffffffffu, h0, 1);
        float n1 = __shfl_xor_sync(0xffffffffu, h1, 1);
        float n2 = __shfl_xor_sync(0xffffffffu, h2, 1);
        float n3 = __shfl_xor_sync(0xffffffffu, h3, 1);
        if (!(lane & 1)) {
            int w = lane >> 1;
            __half2 q0 = __floats2half2_rn(h0, n0);
            __half2 q1 = __floats2half2_rn(h1, n1);
            __half2 q2 = __floats2half2_rn(h2, n2);
            __half2 q3 = __floats2half2_rn(h3, n3);
            hw[w]      = *reinterpret_cast<unsigned*>(&q0);
            hw[16 + w] = *reinterpret_cast<unsigned*>(&q1);
            hw[32 + w] = *reinterpret_cast<unsigned*>(&q2);
            hw[48 + w] = *reinterpret_cast<unsigned*>(&q3);
        }
        __syncwarp();

        float m0 = contract_msg(hw, 0,  p.x, lane);
        float m1 = contract_msg(hw, 4,  p.z, lane);
        float m2 = contract_msg(hw, 8,  q.x, lane);
        float m3 = contract_msg(hw, 12, q.z, lane);
        __syncwarp();          // all reads done before next iteration's stores

        scatter_msg(m0, p.y, lane);
        scatter_msg(m1, p.w, lane);
        scatter_msg(m2, q.y, lane);
        scatter_msg(m3, q.w, lane);
    }
    for (; e < E; e++) {
        int2 sd = ed_pair[e];
        float h0 = layer1(e, ea, w1r, b1r);
        float n0 = __shfl_xor_sync(0xffffffffu, h0, 1);
        if (!(lane & 1)) {
            __half2 q0 = __floats2half2_rn(h0, n0);
            hw[lane >> 1] = *reinterpret_cast<unsigned*>(&q0);
        }
        __syncwarp();
        float m0 = contract_msg(hw, 0, sd.x, lane);
        __syncwarp();
        scatter_msg(m0, sd.y, lane);
    }
}

// ---------------------------------------------------------------------------
// Finalize: out[n][o] = sum[n][o]/max(indeg,1) + x[n]@root[:,o] + bias[o]
// ---------------------------------------------------------------------------
__global__ void finalize_kernel(const float* __restrict__ x,
                                const float* __restrict__ root,
                                const float* __restrict__ bias,
                                float* __restrict__ out, int N) {
    int idx = blockIdx.x * blockDim.x + threadIdx.x;
    if (idx >= N * 16) return;
    int n = idx >> 4;
    int o = idx & 15;
    float c = (float)deg_dst[n];
    float a = sum_buf[idx] / fmaxf(c, 1.0f);
    float r = 0.f;
#pragma unroll
    for (int i = 0; i < 16; i++) r = fmaf(x[n * 16 + i], root[i * 16 + o], r);
    out[idx] = a + r + bias[o];
}

extern "C" void kernel_launch(void* const* d_in, const int* in_sizes, int n_in,
                              void* d_out, int out_size) {
    const float* x    = (const float*)d_in[0];
    const void*  ei   = d_in[1];
    const float* ea   = (const float*)d_in[2];
    const float* w1   = (const float*)d_in[3];
    const float* b1   = (const float*)d_in[4];
    const float* w2   = (const float*)d_in[5];
    const float* b2   = (const float*)d_in[6];
    const float* root = (const float*)d_in[7];
    const float* bias = (const float*)d_in[8];
    float*       out  = (float*)d_out;

    int N = in_sizes[0] / 16;
    int E = in_sizes[2] / 16;

    setup_kernel<<<(N * 16 + 255) / 256, 256>>>(w2, (const int*)ei, N);
    decode_hist_kernel<<<(E + 255) / 256, 256>>>(ei, E);

    node_pre_kernel<<<(N + NODES_PER_BLOCK - 1) / NODES_PER_BLOCK, 128>>>(x, b2, N);

    edge_kernel<<<2048, 256>>>(ea, w1, b1, E);

    finalize_kernel<<<(N * 16 + 255) / 256, 256>>>(x, root, bias, out, N);
}